// round 3
// baseline (speedup 1.0000x reference)
#include <cuda_runtime.h>
#include <math.h>

#define BATCH 2048
#define FEAT  2048
#define HARM  32
#define DIN   (FEAT + 2*HARM)   /* 2112 */
#define NEXP  8
#define EDIM  32
#define HID   1024
#define VOCAB 50257

// -------- scratch (no allocations allowed) --------
__device__ __align__(16) float g_ctx[BATCH * HID];   // 8 MB
__device__ __align__(16) float g_gain[HID];

// ============================================================
// Kernel 1: per-sample fused pipeline up to ctx = tanh(mixed@Wo+bo)
//   one block per sample, 256 threads
// ============================================================
__global__ __launch_bounds__(256) void fused_ctx_kernel(
    const float* __restrict__ x,
    const float* __restrict__ Wg, const float* __restrict__ bg,
    const float* __restrict__ We, const float* __restrict__ be,
    const float* __restrict__ Wo, const float* __restrict__ bo)
{
    __shared__ __align__(16) float enh[DIN];
    __shared__ float red[256];
    __shared__ float logits[NEXP];
    __shared__ float eo_s[NEXP * EDIM];
    __shared__ float gate[NEXP];
    __shared__ float mixed[EDIM];

    const int b = blockIdx.x;
    const int t = threadIdx.x;
    const float* xr = x + (size_t)b * FEAT;

    // load x row into smem + partial sum for mean
    float sum = 0.f;
    for (int i = t; i < FEAT; i += 256) {
        float v = xr[i];
        enh[i] = v;
        sum += v;
    }
    red[t] = sum;
    __syncthreads();
    for (int s = 128; s > 0; s >>= 1) {
        if (t < s) red[t] += red[t + s];
        __syncthreads();
    }
    float smean = red[0] * (1.0f / FEAT);

    // phasor features: enh[FEAT + j], j<32 -> cos(k*base), j>=32 -> sin
    if (t < 2 * HARM) {
        int kk = (t & (HARM - 1)) + 1;
        float base = 43.98229715025711f * smean;   // 2*pi*7 in f32
        float ph = base * (float)kk;
        enh[FEAT + t] = (t < HARM) ? cosf(ph) : sinf(ph);
    }
    __syncthreads();

    // 264 dot products of length DIN
    for (int j = t; j < NEXP + NEXP * EDIM; j += 256) {
        float acc = 0.f;
        if (j < NEXP) {
            const float* w = Wg + j;
            #pragma unroll 8
            for (int d = 0; d < DIN; d++)
                acc = fmaf(enh[d], w[(size_t)d * NEXP], acc);
            logits[j] = acc + bg[j];
        } else {
            int jj = j - NEXP;
            int e = jj >> 5, h = jj & 31;
            const float* w = We + (size_t)e * DIN * EDIM + h;
            #pragma unroll 8
            for (int d = 0; d < DIN; d++)
                acc = fmaf(enh[d], w[(size_t)d * EDIM], acc);
            eo_s[jj] = acc + be[jj];
        }
    }
    __syncthreads();

    // softmax over 8 experts
    if (t == 0) {
        float mx = logits[0];
        #pragma unroll
        for (int e = 1; e < NEXP; e++) mx = fmaxf(mx, logits[e]);
        float ss = 0.f;
        #pragma unroll
        for (int e = 0; e < NEXP; e++) { float ex = expf(logits[e] - mx); gate[e] = ex; ss += ex; }
        float inv = 1.0f / ss;
        #pragma unroll
        for (int e = 0; e < NEXP; e++) gate[e] *= inv;
    }
    __syncthreads();

    // mixed[h] = sum_e gate[e]*eo[e][h]
    if (t < EDIM) {
        float m = 0.f;
        #pragma unroll
        for (int e = 0; e < NEXP; e++) m = fmaf(gate[e], eo_s[e * EDIM + t], m);
        mixed[t] = m;
    }
    __syncthreads();

    // ctx = tanh(mixed @ Wo + bo)
    for (int o = t; o < HID; o += 256) {
        float acc = bo[o];
        #pragma unroll
        for (int k = 0; k < EDIM; k++)
            acc = fmaf(mixed[k], Wo[(size_t)k * HID + o], acc);
        g_ctx[(size_t)b * HID + o] = tanhf(acc);
    }
}

// ============================================================
// Kernel 2: top-20 of ctx[0,:] -> gain (2.0 on winners, else 1.0)
// (the LIF k-winner scan collapses to this: each distinct token
//  spikes exactly once -> cnt=1 on the 20 argsort-top indices)
// ============================================================
__global__ __launch_bounds__(256) void topk_gain_kernel()
{
    __shared__ float vals[HID];
    __shared__ float rv[256];
    __shared__ int   ri[256];
    const int t = threadIdx.x;

    for (int i = t; i < HID; i += 256) {
        vals[i] = g_ctx[i];
        g_gain[i] = 1.0f;
    }
    __syncthreads();

    for (int it = 0; it < 20; it++) {
        float best = -1e30f; int bi = 0;
        for (int i = t; i < HID; i += 256) {
            if (vals[i] > best) { best = vals[i]; bi = i; }
        }
        rv[t] = best; ri[t] = bi;
        __syncthreads();
        for (int s = 128; s > 0; s >>= 1) {
            if (t < s) {
                if (rv[t + s] > rv[t]) { rv[t] = rv[t + s]; ri[t] = ri[t + s]; }
            }
            __syncthreads();
        }
        if (t == 0) {
            g_gain[ri[0]] = 2.0f;
            vals[ri[0]] = -1e30f;
        }
        __syncthreads();
    }
}

// ============================================================
// Kernel 3: out = (ctx * gain) @ Wout + bout
// 128x128x8 tiled fp32 GEMM, 8x8 per thread, packed fma.rn.f32x2
// NOTE: Wout rows have ODD stride (50257 floats) -> row bases are only
// 4B-aligned. B-tile global loads MUST be 32-bit scalars.
// ============================================================
#define BM 128
#define BN 128
#define BK 8

__global__ __launch_bounds__(256) void gemm_out_kernel(
    const float* __restrict__ Bm,     // Wout [K,N]
    const float* __restrict__ bias,   // bout [N]
    float* __restrict__ C)            // out [M,N]
{
    const int N = VOCAB, K = HID;
    __shared__ __align__(16) float As[BK][BM];
    __shared__ __align__(16) float Bs[BK][BN];

    const int tid = threadIdx.x;
    const int m0 = blockIdx.x * BM;   // M fastest -> B tiles shared in L2 per wave
    const int n0 = blockIdx.y * BN;
    const int tx = tid & 15;
    const int ty = tid >> 4;

    const int a_row = tid >> 1;
    const int a_col = (tid & 1) << 2;
    const int b_row = tid >> 5;
    const int b_col = (tid & 31) << 2;

    unsigned long long acc2[8][4];
    #pragma unroll
    for (int i = 0; i < 8; i++)
        #pragma unroll
        for (int j = 0; j < 4; j++) acc2[i][j] = 0ULL;

    for (int k0 = 0; k0 < K; k0 += BK) {
        // A tile (gain fused) -> transposed smem layout
        // g_ctx row stride = 1024 floats (16B multiple) -> float4 safe
        float4 av = *(const float4*)(g_ctx + (size_t)(m0 + a_row) * K + k0 + a_col);
        float4 gv = *(const float4*)(g_gain + k0 + a_col);
        As[a_col + 0][a_row] = av.x * gv.x;
        As[a_col + 1][a_row] = av.y * gv.y;
        As[a_col + 2][a_row] = av.z * gv.z;
        As[a_col + 3][a_row] = av.w * gv.w;

        // B tile: scalar 32-bit loads (odd row stride), guarded on N edge
        {
            int c = n0 + b_col;
            const float* brow = Bm + (size_t)(k0 + b_row) * N;
            float b0 = (c + 0 < N) ? __ldg(brow + c + 0) : 0.f;
            float b1 = (c + 1 < N) ? __ldg(brow + c + 1) : 0.f;
            float b2 = (c + 2 < N) ? __ldg(brow + c + 2) : 0.f;
            float b3 = (c + 3 < N) ? __ldg(brow + c + 3) : 0.f;
            Bs[b_row][b_col + 0] = b0;
            Bs[b_row][b_col + 1] = b1;
            Bs[b_row][b_col + 2] = b2;
            Bs[b_row][b_col + 3] = b3;
        }
        __syncthreads();

        #pragma unroll
        for (int k = 0; k < BK; k++) {
            float4 a0 = *(const float4*)&As[k][ty * 8];
            float4 a1 = *(const float4*)&As[k][ty * 8 + 4];
            const unsigned long long* bp =
                (const unsigned long long*)&Bs[k][tx * 8];
            unsigned long long rb0 = bp[0], rb1 = bp[1], rb2v = bp[2], rb3 = bp[3];
            float ra[8] = {a0.x, a0.y, a0.z, a0.w, a1.x, a1.y, a1.z, a1.w};
            #pragma unroll
            for (int i = 0; i < 8; i++) {
                unsigned long long av2;
                unsigned int au = __float_as_uint(ra[i]);
                asm("mov.b64 %0, {%1, %1};" : "=l"(av2) : "r"(au));
                asm("fma.rn.f32x2 %0, %1, %2, %0;" : "+l"(acc2[i][0]) : "l"(av2), "l"(rb0));
                asm("fma.rn.f32x2 %0, %1, %2, %0;" : "+l"(acc2[i][1]) : "l"(av2), "l"(rb1));
                asm("fma.rn.f32x2 %0, %1, %2, %0;" : "+l"(acc2[i][2]) : "l"(av2), "l"(rb2v));
                asm("fma.rn.f32x2 %0, %1, %2, %0;" : "+l"(acc2[i][3]) : "l"(av2), "l"(rb3));
            }
        }
        __syncthreads();
    }

    // epilogue: + bias, guarded scalar stores (out rows also odd-strided)
    #pragma unroll
    for (int i = 0; i < 8; i++) {
        int row = m0 + ty * 8 + i;
        float* crow = C + (size_t)row * N;
        #pragma unroll
        for (int j = 0; j < 4; j++) {
            int c0 = n0 + tx * 8 + 2 * j;
            float v0 = __uint_as_float((unsigned)(acc2[i][j] & 0xffffffffULL));
            float v1 = __uint_as_float((unsigned)(acc2[i][j] >> 32));
            if (c0 < N)     crow[c0]     = v0 + bias[c0];
            if (c0 + 1 < N) crow[c0 + 1] = v1 + bias[c0 + 1];
        }
    }
}

// ============================================================
extern "C" void kernel_launch(void* const* d_in, const int* in_sizes, int n_in,
                              void* d_out, int out_size)
{
    const float* x    = (const float*)d_in[0];   // [2048,2048]
    const float* Wg   = (const float*)d_in[1];   // [2112,8]
    const float* bg   = (const float*)d_in[2];   // [8]
    const float* We   = (const float*)d_in[3];   // [8,2112,32]
    const float* be   = (const float*)d_in[4];   // [8,32]
    const float* Wo   = (const float*)d_in[5];   // [32,1024]
    const float* bo   = (const float*)d_in[6];   // [1024]
    const float* Wout = (const float*)d_in[7];   // [1024,50257]
    const float* bout = (const float*)d_in[8];   // [50257]
    float* out = (float*)d_out;

    fused_ctx_kernel<<<BATCH, 256>>>(x, Wg, bg, We, be, Wo, bo);
    topk_gain_kernel<<<1, 256>>>();
    dim3 grid(BATCH / BM, (VOCAB + BN - 1) / BN);
    gemm_out_kernel<<<grid, 256>>>(Wout, bout, out);
}

// round 5
// speedup vs baseline: 2.5160x; 2.5160x over previous
#include <cuda_runtime.h>
#include <cuda_fp16.h>
#include <math.h>
#include <stdint.h>

#define BATCH 2048
#define FEAT  2048
#define HARM  32
#define DIN   (FEAT + 2*HARM)   /* 2112 */
#define NEXP  8
#define EDIM  32
#define HID   1024
#define VOCAB 50257
#define NPAD  50432             /* 394 * 128 */
#define NT128 394
#define MT128 16

// ---------------- device scratch (no allocations allowed) ----------------
__device__ __align__(16) float  g_ctx[BATCH * HID];          // 8 MB
__device__ __align__(16) float  g_gain[HID];
__device__ __align__(16) __half g_A_hi[BATCH * HID];         // [2048][1024]
__device__ __align__(16) __half g_A_lo[BATCH * HID];
__device__ __align__(16) __half g_B_hi[(size_t)NPAD * HID];  // [NPAD][1024] (Wout^T)
__device__ __align__(16) __half g_B_lo[(size_t)NPAD * HID];

__device__ __forceinline__ uint32_t smem_u32(const void* p) {
    uint32_t a;
    asm("{ .reg .u64 t; cvta.to.shared.u64 t, %1; cvt.u32.u64 %0, t; }" : "=r"(a) : "l"(p));
    return a;
}

#define LDSM_X4(r, a) asm volatile( \
    "ldmatrix.sync.aligned.m8n8.x4.shared.b16 {%0,%1,%2,%3}, [%4];" \
    : "=r"((r)[0]),"=r"((r)[1]),"=r"((r)[2]),"=r"((r)[3]) : "r"(a))
#define LDSM_X2(r, a) asm volatile( \
    "ldmatrix.sync.aligned.m8n8.x2.shared.b16 {%0,%1}, [%2];" \
    : "=r"((r)[0]),"=r"((r)[1]) : "r"(a))
#define MMA16816(c, a, b) asm volatile( \
    "mma.sync.aligned.m16n8k16.row.col.f32.f16.f16.f32 " \
    "{%0,%1,%2,%3},{%4,%5,%6,%7},{%8,%9},{%0,%1,%2,%3};" \
    : "+f"((c)[0]),"+f"((c)[1]),"+f"((c)[2]),"+f"((c)[3]) \
    : "r"((a)[0]),"r"((a)[1]),"r"((a)[2]),"r"((a)[3]), "r"((b)[0]),"r"((b)[1]))
#define CP_ASYNC16(d, s) asm volatile( \
    "cp.async.cg.shared.global [%0], [%1], 16;" :: "r"(d), "l"(s) : "memory")
#define CP_COMMIT() asm volatile("cp.async.commit_group;" ::: "memory")
#define CP_WAIT0()  asm volatile("cp.async.wait_group 0;" ::: "memory")

// ============================================================
// Kernel 1: fused ctx — 16 samples per block, 128 blocks
// ============================================================
__global__ __launch_bounds__(256) void fused_ctx_kernel(
    const float* __restrict__ x,
    const float* __restrict__ Wg, const float* __restrict__ bg,
    const float* __restrict__ We, const float* __restrict__ be,
    const float* __restrict__ Wo, const float* __restrict__ bo)
{
    extern __shared__ __align__(16) char sm[];
    float* enh    = (float*)sm;                          // [16][2112]
    float* eo_s   = (float*)(sm + 16*DIN*4);             // [16][256]
    float* logits = (float*)(sm + 16*DIN*4 + 16*256*4);  // [16][8]
    float* mixed  = logits + 16*8;                       // [16][32]

    const int t = threadIdx.x;
    const int wid = t >> 5, lane = t & 31;
    const int b0 = blockIdx.x * 16;

    // phase 1: each warp handles 2 samples: load row, mean, phasor
    for (int sh = 0; sh < 2; sh++) {
        int s = wid * 2 + sh;
        const float4* xr = (const float4*)(x + (size_t)(b0 + s) * FEAT);
        float* er = enh + s * DIN;
        float sum = 0.f;
        #pragma unroll 4
        for (int i = lane; i < FEAT/4; i += 32) {
            float4 v = xr[i];
            *(float4*)(er + 4*i) = v;
            sum += (v.x + v.y) + (v.z + v.w);
        }
        #pragma unroll
        for (int o = 16; o > 0; o >>= 1) sum += __shfl_xor_sync(0xffffffffu, sum, o);
        float mean = sum * (1.0f / FEAT);
        float base = 43.98229715025711f * mean;   // 2*pi*7
        float ph = base * (float)(lane + 1);
        er[FEAT + lane]        = cosf(ph);
        er[FEAT + HARM + lane] = sinf(ph);
    }
    __syncthreads();

    // phase 2: 264 dot products of length DIN for 16 samples at once
    for (int jj = t; jj < NEXP + NEXP*EDIM; jj += 256) {
        float acc[16];
        #pragma unroll
        for (int s = 0; s < 16; s++) acc[s] = 0.f;
        const float* wp; long stride;
        if (jj < NEXP) { wp = Wg + jj; stride = NEXP; }
        else { int e = (jj - NEXP) >> 5, h = (jj - NEXP) & 31;
               wp = We + (size_t)e * DIN * EDIM + h; stride = EDIM; }
        for (int d = 0; d < DIN; d += 4) {
            float w0 = wp[(long)(d+0)*stride];
            float w1 = wp[(long)(d+1)*stride];
            float w2 = wp[(long)(d+2)*stride];
            float w3 = wp[(long)(d+3)*stride];
            #pragma unroll
            for (int s = 0; s < 16; s++) {
                float4 ev = *(const float4*)(enh + s*DIN + d);
                float a = acc[s];
                a = fmaf(ev.x, w0, a); a = fmaf(ev.y, w1, a);
                a = fmaf(ev.z, w2, a); a = fmaf(ev.w, w3, a);
                acc[s] = a;
            }
        }
        if (jj < NEXP) {
            #pragma unroll
            for (int s = 0; s < 16; s++) logits[s*8 + jj] = acc[s] + bg[jj];
        } else {
            #pragma unroll
            for (int s = 0; s < 16; s++) eo_s[s*256 + (jj - NEXP)] = acc[s] + be[jj - NEXP];
        }
    }
    __syncthreads();

    // phase 3: softmax per sample
    if (t < 16) {
        float* lg = logits + t*8;
        float mx = lg[0];
        #pragma unroll
        for (int e = 1; e < 8; e++) mx = fmaxf(mx, lg[e]);
        float ss = 0.f;
        #pragma unroll
        for (int e = 0; e < 8; e++) { float ex = expf(lg[e] - mx); lg[e] = ex; ss += ex; }
        float inv = 1.0f / ss;
        #pragma unroll
        for (int e = 0; e < 8; e++) lg[e] *= inv;
    }
    __syncthreads();

    // phase 4: mixed
    for (int v = t; v < 16*32; v += 256) {
        int s = v >> 5, h = v & 31;
        float m = 0.f;
        #pragma unroll
        for (int e = 0; e < 8; e++) m = fmaf(logits[s*8 + e], eo_s[s*256 + e*32 + h], m);
        mixed[v] = m;
    }
    __syncthreads();

    // phase 5: ctx = tanh(mixed @ Wo + bo)
    for (int it = 0; it < 4; it++) {
        int o = t + it * 256;
        float acc[16];
        float bb = bo[o];
        #pragma unroll
        for (int s = 0; s < 16; s++) acc[s] = bb;
        for (int k = 0; k < EDIM; k++) {
            float w = Wo[(size_t)k * HID + o];
            #pragma unroll
            for (int s = 0; s < 16; s++) acc[s] = fmaf(mixed[s*32 + k], w, acc[s]);
        }
        #pragma unroll
        for (int s = 0; s < 16; s++)
            g_ctx[(size_t)(b0 + s) * HID + o] = tanhf(acc[s]);
    }
}

// ============================================================
// Kernel 2: top-20 of ctx[0,:] -> gain (spiking scan collapses)
// ============================================================
__global__ __launch_bounds__(256) void topk_gain_kernel()
{
    __shared__ float vals[HID];
    __shared__ float rv[256];
    __shared__ int   ri[256];
    const int t = threadIdx.x;
    for (int i = t; i < HID; i += 256) { vals[i] = g_ctx[i]; g_gain[i] = 1.0f; }
    __syncthreads();
    for (int it = 0; it < 20; it++) {
        float best = -1e30f; int bi = 0;
        for (int i = t; i < HID; i += 256)
            if (vals[i] > best) { best = vals[i]; bi = i; }
        rv[t] = best; ri[t] = bi;
        __syncthreads();
        for (int s = 128; s > 0; s >>= 1) {
            if (t < s && rv[t + s] > rv[t]) { rv[t] = rv[t + s]; ri[t] = ri[t + s]; }
            __syncthreads();
        }
        if (t == 0) { g_gain[ri[0]] = 2.0f; vals[ri[0]] = -1e30f; }
        __syncthreads();
    }
}

// ============================================================
// Kernel 3: convert ctx*gain -> fp16 hi + residual lo, plain [M][K]
// ============================================================
__global__ __launch_bounds__(256) void convert_ctx_kernel()
{
    int idx = blockIdx.x * 256 + threadIdx.x;   // 2048*512 pair slots
    int mr = idx >> 9;
    int k  = (idx & 511) * 2;
    float2 v = *(const float2*)(g_ctx + (size_t)mr * HID + k);
    float2 g = *(const float2*)(g_gain + k);
    float a0 = v.x * g.x, a1 = v.y * g.y;
    __half h0 = __float2half_rn(a0);
    __half h1 = __float2half_rn(a1);
    __half l0 = __float2half_rn(a0 - __half2float(h0));
    __half l1 = __float2half_rn(a1 - __half2float(h1));
    uint32_t hi = (uint32_t)__half_as_ushort(h0) | ((uint32_t)__half_as_ushort(h1) << 16);
    uint32_t lo = (uint32_t)__half_as_ushort(l0) | ((uint32_t)__half_as_ushort(l1) << 16);
    size_t e = (size_t)mr * HID + k;
    *(uint32_t*)((__half*)g_A_hi + e) = hi;
    *(uint32_t*)((__half*)g_A_lo + e) = lo;
}

// ============================================================
// Kernel 4: Wout [K][N] f32 -> g_B_{hi,lo} [NPAD][K] fp16, transpose
// grid (16 kchunks of 64, 394 n-tiles of 128)
// ============================================================
__global__ __launch_bounds__(256) void convert_wout_kernel(const float* __restrict__ W)
{
    __shared__ uint16_t s_hi[128][66];
    __shared__ uint16_t s_lo[128][66];
    const int t = threadIdx.x;
    const int k0 = blockIdx.x * 64;
    const int n0 = blockIdx.y * 128;

    for (int it = 0; it < 32; it++) {
        int idx = it * 256 + t;        // 64k x 128n
        int k = idx >> 7, n = idx & 127;
        int gn = n0 + n;
        float v = (gn < VOCAB) ? __ldg(W + (size_t)(k0 + k) * VOCAB + gn) : 0.f;
        __half h = __float2half_rn(v);
        __half l = __float2half_rn(v - __half2float(h));
        s_hi[n][k] = __half_as_ushort(h);
        s_lo[n][k] = __half_as_ushort(l);
    }
    __syncthreads();

    for (int it = 0; it < 16; it++) {
        int u = it * 256 + t;          // 128 n-rows x 32 uint32
        int nn = u >> 5, ku = (u & 31) * 2;
        uint32_t hv = *(uint32_t*)&s_hi[nn][ku];
        uint32_t lv = *(uint32_t*)&s_lo[nn][ku];
        size_t e = (size_t)(n0 + nn) * HID + k0 + ku;
        *(uint32_t*)((__half*)g_B_hi + e) = hv;
        *(uint32_t*)((__half*)g_B_lo + e) = lv;
    }
}

// ============================================================
// Kernel 5: out = A @ B^T + bias via mma.sync fp16 split (3 products)
// CTA 128x128, BK=64, 2-stage cp.async pipeline, 8 warps of 32x64
// ============================================================
#define BK 64
#define SROW 72                        /* fp16 per smem row (pad 8) */
#define ARR_B (128 * SROW * 2)         /* 18432 B per array */
#define STG_B (4 * ARR_B)              /* 73728 B per stage */

__global__ __launch_bounds__(256) void gemm_mma_kernel(
    const float* __restrict__ bias, float* __restrict__ C)
{
    extern __shared__ __align__(16) char sm[];
    const uint32_t sb = smem_u32(sm);
    const int t = threadIdx.x, lane = t & 31, wid = t >> 5;
    const int m0 = blockIdx.x * 128, n0 = blockIdx.y * 128;
    const int m0w = (wid & 3) * 32, n0w = (wid >> 2) * 64;

    float acc[2][8][4];
    #pragma unroll
    for (int i = 0; i < 2; i++)
        #pragma unroll
        for (int j = 0; j < 8; j++)
            #pragma unroll
            for (int q = 0; q < 4; q++) acc[i][j][q] = 0.f;

    const __half* srcs[4] = {
        g_A_hi + (size_t)m0 * HID, g_A_lo + (size_t)m0 * HID,
        g_B_hi + (size_t)n0 * HID, g_B_lo + (size_t)n0 * HID };

    // ---- async stage loader ----
    auto issue = [&](int c) {
        uint32_t stg = sb + (uint32_t)(c & 1) * STG_B;
        int k0 = c * BK;
        #pragma unroll
        for (int a = 0; a < 4; a++) {
            uint32_t dbase = stg + a * ARR_B;
            const __half* gp = srcs[a] + k0;
            #pragma unroll
            for (int it = 0; it < 4; it++) {
                int idx = it * 256 + t;
                int row = idx >> 3, seg = idx & 7;
                uint32_t d = dbase + row * (SROW * 2) + seg * 16;
                CP_ASYNC16(d, gp + (size_t)row * HID + seg * 8);
            }
        }
        CP_COMMIT();
    };

    issue(0);
    for (int c = 0; c < HID / BK; c++) {
        CP_WAIT0();
        __syncthreads();
        if (c + 1 < HID / BK) issue(c + 1);

        uint32_t stg = sb + (uint32_t)(c & 1) * STG_B;
        uint32_t pAh = stg, pAl = stg + ARR_B, pBh = stg + 2*ARR_B, pBl = stg + 3*ARR_B;

        #pragma unroll
        for (int ks = 0; ks < 4; ks++) {
            int kb = ks * 16;
            uint32_t acol = (uint32_t)(kb + ((lane >> 4) << 3)) * 2;
            uint32_t bcol = (uint32_t)(kb + (((lane >> 3) & 1) << 3)) * 2;

            uint32_t ah[2][4], al[2][4];
            #pragma unroll
            for (int mt = 0; mt < 2; mt++) {
                uint32_t ra = (uint32_t)(m0w + mt*16 + (lane & 15)) * (SROW*2) + acol;
                LDSM_X4(ah[mt], pAh + ra);
                LDSM_X4(al[mt], pAl + ra);
            }
            uint32_t bh[8][2], bl[8][2];
            #pragma unroll
            for (int nt = 0; nt < 8; nt++) {
                uint32_t rb = (uint32_t)(n0w + nt*8 + (lane & 7)) * (SROW*2) + bcol;
                LDSM_X2(bh[nt], pBh + rb);
                LDSM_X2(bl[nt], pBl + rb);
            }
            #pragma unroll
            for (int mt = 0; mt < 2; mt++)
                #pragma unroll
                for (int nt = 0; nt < 8; nt++) {
                    MMA16816(acc[mt][nt], ah[mt], bh[nt]);
                    MMA16816(acc[mt][nt], ah[mt], bl[nt]);
                    MMA16816(acc[mt][nt], al[mt], bh[nt]);
                }
        }
    }

    // ---- epilogue: + bias, store (float2 on even rows) ----
    const bool full = (n0 + 128 <= VOCAB);
    #pragma unroll
    for (int mt = 0; mt < 2; mt++) {
        int r0 = m0 + m0w + mt*16 + (lane >> 2);      // r1 = r0 + 8
        #pragma unroll
        for (int nt = 0; nt < 8; nt++) {
            int cn = n0 + n0w + nt*8 + ((lane & 3) << 1);
            float* c0p = C + (size_t)r0 * VOCAB + cn;
            float* c1p = c0p + (size_t)8 * VOCAB;
            if (full) {
                float b0 = __ldg(bias + cn), b1 = __ldg(bias + cn + 1);
                float v0 = acc[mt][nt][0] + b0, v1 = acc[mt][nt][1] + b1;
                float v2 = acc[mt][nt][2] + b0, v3 = acc[mt][nt][3] + b1;
                if (!(r0 & 1)) {        // element index even -> 8B aligned
                    *(float2*)c0p = make_float2(v0, v1);
                    *(float2*)c1p = make_float2(v2, v3);
                } else {
                    c0p[0] = v0; c0p[1] = v1;
                    c1p[0] = v2; c1p[1] = v3;
                }
            } else {
                if (cn < VOCAB) {
                    float b0 = __ldg(bias + cn);
                    c0p[0] = acc[mt][nt][0] + b0;
                    c1p[0] = acc[mt][nt][2] + b0;
                }
                if (cn + 1 < VOCAB) {
                    float b1 = __ldg(bias + cn + 1);
                    c0p[1] = acc[mt][nt][1] + b1;
                    c1p[1] = acc[mt][nt][3] + b1;
                }
            }
        }
    }
}

// ============================================================
extern "C" void kernel_launch(void* const* d_in, const int* in_sizes, int n_in,
                              void* d_out, int out_size)
{
    const float* x    = (const float*)d_in[0];
    const float* Wg   = (const float*)d_in[1];
    const float* bg   = (const float*)d_in[2];
    const float* We   = (const float*)d_in[3];
    const float* be   = (const float*)d_in[4];
    const float* Wo   = (const float*)d_in[5];
    const float* bo   = (const float*)d_in[6];
    const float* Wout = (const float*)d_in[7];
    const float* bout = (const float*)d_in[8];
    float* out = (float*)d_out;

    const int ctx_smem  = 16*DIN*4 + 16*256*4 + 16*8*4 + 16*32*4;   // 154112
    const int gemm_smem = 2 * STG_B;                                 // 147456
    cudaFuncSetAttribute(fused_ctx_kernel, cudaFuncAttributeMaxDynamicSharedMemorySize, ctx_smem);
    cudaFuncSetAttribute(gemm_mma_kernel,  cudaFuncAttributeMaxDynamicSharedMemorySize, gemm_smem);

    convert_wout_kernel<<<dim3(16, NT128), 256>>>(Wout);
    fused_ctx_kernel<<<BATCH/16, 256, ctx_smem>>>(x, Wg, bg, We, be, Wo, bo);
    topk_gain_kernel<<<1, 256>>>();
    convert_ctx_kernel<<<(BATCH*HID/2)/256, 256>>>();
    gemm_mma_kernel<<<dim3(MT128, NT128), 256, gemm_smem>>>(bout, out);
}

// round 6
// speedup vs baseline: 3.0539x; 1.2138x over previous
#include <cuda_runtime.h>
#include <cuda_fp16.h>
#include <math.h>
#include <stdint.h>

#define BATCH 2048
#define FEAT  2048
#define HARM  32
#define DIN   (FEAT + 2*HARM)   /* 2112 */
#define NEXP  8
#define EDIM  32
#define HID   1024
#define VOCAB 50257
#define NPAD  50432             /* 394 * 128 */
#define NT128 394
#define MT128 16

// ---------------- device scratch (no allocations allowed) ----------------
__device__ __align__(16) float  g_ctx[BATCH * HID];          // 8 MB
__device__ __align__(16) float  g_gain[HID];
__device__ __align__(16) __half g_A_hi[BATCH * HID];         // [2048][1024]
__device__ __align__(16) __half g_A_lo[BATCH * HID];         // residual
__device__ __align__(16) __half g_B_hi[(size_t)NPAD * HID];  // [NPAD][1024] (Wout^T)

__device__ __forceinline__ uint32_t smem_u32(const void* p) {
    uint32_t a;
    asm("{ .reg .u64 t; cvta.to.shared.u64 t, %1; cvt.u32.u64 %0, t; }" : "=r"(a) : "l"(p));
    return a;
}

#define LDSM_X4(r, a) asm volatile( \
    "ldmatrix.sync.aligned.m8n8.x4.shared.b16 {%0,%1,%2,%3}, [%4];" \
    : "=r"((r)[0]),"=r"((r)[1]),"=r"((r)[2]),"=r"((r)[3]) : "r"(a))
#define LDSM_X2(r, a) asm volatile( \
    "ldmatrix.sync.aligned.m8n8.x2.shared.b16 {%0,%1}, [%2];" \
    : "=r"((r)[0]),"=r"((r)[1]) : "r"(a))
#define MMA16816(c, a, b) asm volatile( \
    "mma.sync.aligned.m16n8k16.row.col.f32.f16.f16.f32 " \
    "{%0,%1,%2,%3},{%4,%5,%6,%7},{%8,%9},{%0,%1,%2,%3};" \
    : "+f"((c)[0]),"+f"((c)[1]),"+f"((c)[2]),"+f"((c)[3]) \
    : "r"((a)[0]),"r"((a)[1]),"r"((a)[2]),"r"((a)[3]), "r"((b)[0]),"r"((b)[1]))
#define CP_ASYNC16(d, s) asm volatile( \
    "cp.async.cg.shared.global [%0], [%1], 16;" :: "r"(d), "l"(s) : "memory")
#define CP_COMMIT() asm volatile("cp.async.commit_group;" ::: "memory")
#define CP_WAIT1()  asm volatile("cp.async.wait_group 1;" ::: "memory")
#define CP_WAIT0()  asm volatile("cp.async.wait_group 0;" ::: "memory")

// ============================================================
// Kernel 1: fused ctx — 16 samples per block, 128 blocks
// ============================================================
__global__ __launch_bounds__(256) void fused_ctx_kernel(
    const float* __restrict__ x,
    const float* __restrict__ Wg, const float* __restrict__ bg,
    const float* __restrict__ We, const float* __restrict__ be,
    const float* __restrict__ Wo, const float* __restrict__ bo)
{
    extern __shared__ __align__(16) char sm[];
    float* enh    = (float*)sm;                          // [16][2112]
    float* eo_s   = (float*)(sm + 16*DIN*4);             // [16][256]
    float* logits = (float*)(sm + 16*DIN*4 + 16*256*4);  // [16][8]
    float* mixed  = logits + 16*8;                       // [16][32]

    const int t = threadIdx.x;
    const int wid = t >> 5, lane = t & 31;
    const int b0 = blockIdx.x * 16;

    for (int sh = 0; sh < 2; sh++) {
        int s = wid * 2 + sh;
        const float4* xr = (const float4*)(x + (size_t)(b0 + s) * FEAT);
        float* er = enh + s * DIN;
        float sum = 0.f;
        #pragma unroll 4
        for (int i = lane; i < FEAT/4; i += 32) {
            float4 v = xr[i];
            *(float4*)(er + 4*i) = v;
            sum += (v.x + v.y) + (v.z + v.w);
        }
        #pragma unroll
        for (int o = 16; o > 0; o >>= 1) sum += __shfl_xor_sync(0xffffffffu, sum, o);
        float mean = sum * (1.0f / FEAT);
        float base = 43.98229715025711f * mean;   // 2*pi*7
        float ph = base * (float)(lane + 1);
        er[FEAT + lane]        = cosf(ph);
        er[FEAT + HARM + lane] = sinf(ph);
    }
    __syncthreads();

    for (int jj = t; jj < NEXP + NEXP*EDIM; jj += 256) {
        float acc[16];
        #pragma unroll
        for (int s = 0; s < 16; s++) acc[s] = 0.f;
        const float* wp; long stride;
        if (jj < NEXP) { wp = Wg + jj; stride = NEXP; }
        else { int e = (jj - NEXP) >> 5, h = (jj - NEXP) & 31;
               wp = We + (size_t)e * DIN * EDIM + h; stride = EDIM; }
        for (int d = 0; d < DIN; d += 4) {
            float w0 = wp[(long)(d+0)*stride];
            float w1 = wp[(long)(d+1)*stride];
            float w2 = wp[(long)(d+2)*stride];
            float w3 = wp[(long)(d+3)*stride];
            #pragma unroll
            for (int s = 0; s < 16; s++) {
                float4 ev = *(const float4*)(enh + s*DIN + d);
                float a = acc[s];
                a = fmaf(ev.x, w0, a); a = fmaf(ev.y, w1, a);
                a = fmaf(ev.z, w2, a); a = fmaf(ev.w, w3, a);
                acc[s] = a;
            }
        }
        if (jj < NEXP) {
            #pragma unroll
            for (int s = 0; s < 16; s++) logits[s*8 + jj] = acc[s] + bg[jj];
        } else {
            #pragma unroll
            for (int s = 0; s < 16; s++) eo_s[s*256 + (jj - NEXP)] = acc[s] + be[jj - NEXP];
        }
    }
    __syncthreads();

    if (t < 16) {
        float* lg = logits + t*8;
        float mx = lg[0];
        #pragma unroll
        for (int e = 1; e < 8; e++) mx = fmaxf(mx, lg[e]);
        float ss = 0.f;
        #pragma unroll
        for (int e = 0; e < 8; e++) { float ex = expf(lg[e] - mx); lg[e] = ex; ss += ex; }
        float inv = 1.0f / ss;
        #pragma unroll
        for (int e = 0; e < 8; e++) lg[e] *= inv;
    }
    __syncthreads();

    for (int v = t; v < 16*32; v += 256) {
        int s = v >> 5, h = v & 31;
        float m = 0.f;
        #pragma unroll
        for (int e = 0; e < 8; e++) m = fmaf(logits[s*8 + e], eo_s[s*256 + e*32 + h], m);
        mixed[v] = m;
    }
    __syncthreads();

    for (int it = 0; it < 4; it++) {
        int o = t + it * 256;
        float acc[16];
        float bb = bo[o];
        #pragma unroll
        for (int s = 0; s < 16; s++) acc[s] = bb;
        for (int k = 0; k < EDIM; k++) {
            float w = Wo[(size_t)k * HID + o];
            #pragma unroll
            for (int s = 0; s < 16; s++) acc[s] = fmaf(mixed[s*32 + k], w, acc[s]);
        }
        #pragma unroll
        for (int s = 0; s < 16; s++)
            g_ctx[(size_t)(b0 + s) * HID + o] = tanhf(acc[s]);
    }
}

// ============================================================
// Kernel 2: top-20 of ctx[0,:] -> gain (spiking scan collapses)
// ============================================================
__global__ __launch_bounds__(256) void topk_gain_kernel()
{
    __shared__ float vals[HID];
    __shared__ float rv[256];
    __shared__ int   ri[256];
    const int t = threadIdx.x;
    for (int i = t; i < HID; i += 256) { vals[i] = g_ctx[i]; g_gain[i] = 1.0f; }
    __syncthreads();
    for (int it = 0; it < 20; it++) {
        float best = -1e30f; int bi = 0;
        for (int i = t; i < HID; i += 256)
            if (vals[i] > best) { best = vals[i]; bi = i; }
        rv[t] = best; ri[t] = bi;
        __syncthreads();
        for (int s = 128; s > 0; s >>= 1) {
            if (t < s && rv[t + s] > rv[t]) { rv[t] = rv[t + s]; ri[t] = ri[t + s]; }
            __syncthreads();
        }
        if (t == 0) { g_gain[ri[0]] = 2.0f; vals[ri[0]] = -1e30f; }
        __syncthreads();
    }
}

// ============================================================
// Kernel 3: convert ctx*gain -> fp16 hi + residual lo, plain [M][K]
// ============================================================
__global__ __launch_bounds__(256) void convert_ctx_kernel()
{
    int idx = blockIdx.x * 256 + threadIdx.x;
    int mr = idx >> 9;
    int k  = (idx & 511) * 2;
    float2 v = *(const float2*)(g_ctx + (size_t)mr * HID + k);
    float2 g = *(const float2*)(g_gain + k);
    float a0 = v.x * g.x, a1 = v.y * g.y;
    __half h0 = __float2half_rn(a0);
    __half h1 = __float2half_rn(a1);
    __half l0 = __float2half_rn(a0 - __half2float(h0));
    __half l1 = __float2half_rn(a1 - __half2float(h1));
    uint32_t hi = (uint32_t)__half_as_ushort(h0) | ((uint32_t)__half_as_ushort(h1) << 16);
    uint32_t lo = (uint32_t)__half_as_ushort(l0) | ((uint32_t)__half_as_ushort(l1) << 16);
    size_t e = (size_t)mr * HID + k;
    *(uint32_t*)((__half*)g_A_hi + e) = hi;
    *(uint32_t*)((__half*)g_A_lo + e) = lo;
}

// ============================================================
// Kernel 4: Wout [K][N] f32 -> g_B_hi [NPAD][K] fp16 (transpose, hi only)
// ============================================================
__global__ __launch_bounds__(256) void convert_wout_kernel(const float* __restrict__ W)
{
    __shared__ uint16_t s_hi[128][66];
    const int t = threadIdx.x;
    const int k0 = blockIdx.x * 64;
    const int n0 = blockIdx.y * 128;

    for (int it = 0; it < 32; it++) {
        int idx = it * 256 + t;        // 64k x 128n
        int k = idx >> 7, n = idx & 127;
        int gn = n0 + n;
        float v = (gn < VOCAB) ? __ldg(W + (size_t)(k0 + k) * VOCAB + gn) : 0.f;
        s_hi[n][k] = __half_as_ushort(__float2half_rn(v));
    }
    __syncthreads();

    for (int it = 0; it < 16; it++) {
        int u = it * 256 + t;          // 128 n-rows x 32 uint32
        int nn = u >> 5, ku = (u & 31) * 2;
        uint32_t hv = *(uint32_t*)&s_hi[nn][ku];
        size_t e = (size_t)(n0 + nn) * HID + k0 + ku;
        *(uint32_t*)((__half*)g_B_hi + e) = hv;
    }
}

// ============================================================
// Kernel 5: out = (Ah+Al) @ Bh^T + bias via mma.sync (2 products)
// CTA 128x128, BK=64, 3-stage cp.async pipeline, 8 warps of 32x64
// ============================================================
#define BK 64
#define SROW 72                        /* fp16 per smem row (pad 8) */
#define ARR_B (128 * SROW * 2)         /* 18432 B per array */
#define STG_B (3 * ARR_B)              /* Ah | Al | Bh = 55296 B */
#define NCHUNK (HID / BK)              /* 16 */

__global__ __launch_bounds__(256) void gemm_mma_kernel(
    const float* __restrict__ bias, float* __restrict__ C)
{
    extern __shared__ __align__(16) char sm[];
    const uint32_t sb = smem_u32(sm);
    const int t = threadIdx.x, lane = t & 31, wid = t >> 5;
    const int m0 = blockIdx.x * 128, n0 = blockIdx.y * 128;
    const int m0w = (wid & 3) * 32, n0w = (wid >> 2) * 64;

    float acc[2][8][4];
    #pragma unroll
    for (int i = 0; i < 2; i++)
        #pragma unroll
        for (int j = 0; j < 8; j++)
            #pragma unroll
            for (int q = 0; q < 4; q++) acc[i][j][q] = 0.f;

    const __half* srcs[3] = {
        g_A_hi + (size_t)m0 * HID, g_A_lo + (size_t)m0 * HID,
        g_B_hi + (size_t)n0 * HID };

    auto issue = [&](int c) {
        uint32_t stg = sb + (uint32_t)(c % 3) * STG_B;
        int k0 = c * BK;
        #pragma unroll
        for (int a = 0; a < 3; a++) {
            uint32_t dbase = stg + a * ARR_B;
            const __half* gp = srcs[a] + k0;
            #pragma unroll
            for (int it = 0; it < 4; it++) {
                int idx = it * 256 + t;
                int row = idx >> 3, seg = idx & 7;
                uint32_t d = dbase + row * (SROW * 2) + seg * 16;
                CP_ASYNC16(d, gp + (size_t)row * HID + seg * 8);
            }
        }
        CP_COMMIT();
    };

    issue(0);
    issue(1);
    for (int c = 0; c < NCHUNK; c++) {
        if (c + 2 < NCHUNK) { CP_WAIT1(); } else { CP_WAIT0(); }
        __syncthreads();
        if (c + 2 < NCHUNK) issue(c + 2);

        uint32_t stg = sb + (uint32_t)(c % 3) * STG_B;
        uint32_t pAh = stg, pAl = stg + ARR_B, pBh = stg + 2*ARR_B;

        #pragma unroll
        for (int ks = 0; ks < 4; ks++) {
            int kb = ks * 16;
            uint32_t acol = (uint32_t)(kb + ((lane >> 4) << 3)) * 2;
            uint32_t bcol = (uint32_t)(kb + (((lane >> 3) & 1) << 3)) * 2;

            uint32_t ah[2][4], al[2][4];
            #pragma unroll
            for (int mt = 0; mt < 2; mt++) {
                uint32_t ra = (uint32_t)(m0w + mt*16 + (lane & 15)) * (SROW*2) + acol;
                LDSM_X4(ah[mt], pAh + ra);
                LDSM_X4(al[mt], pAl + ra);
            }
            uint32_t bh[8][2];
            #pragma unroll
            for (int nt = 0; nt < 8; nt++) {
                uint32_t rb = (uint32_t)(n0w + nt*8 + (lane & 7)) * (SROW*2) + bcol;
                LDSM_X2(bh[nt], pBh + rb);
            }
            #pragma unroll
            for (int mt = 0; mt < 2; mt++)
                #pragma unroll
                for (int nt = 0; nt < 8; nt++) {
                    MMA16816(acc[mt][nt], ah[mt], bh[nt]);
                    MMA16816(acc[mt][nt], al[mt], bh[nt]);
                }
        }
        __syncthreads();
    }

    // ---- epilogue: + bias, store ----
    const bool full = (n0 + 128 <= VOCAB);
    #pragma unroll
    for (int mt = 0; mt < 2; mt++) {
        int r0 = m0 + m0w + mt*16 + (lane >> 2);
        #pragma unroll
        for (int nt = 0; nt < 8; nt++) {
            int cn = n0 + n0w + nt*8 + ((lane & 3) << 1);
            float* c0p = C + (size_t)r0 * VOCAB + cn;
            float* c1p = c0p + (size_t)8 * VOCAB;
            if (full) {
                float b0 = __ldg(bias + cn), b1 = __ldg(bias + cn + 1);
                float v0 = acc[mt][nt][0] + b0, v1 = acc[mt][nt][1] + b1;
                float v2 = acc[mt][nt][2] + b0, v3 = acc[mt][nt][3] + b1;
                if (!(((size_t)r0 * VOCAB + cn) & 1)) {
                    *(float2*)c0p = make_float2(v0, v1);
                } else { c0p[0] = v0; c0p[1] = v1; }
                if (!(((size_t)(r0+8) * VOCAB + cn) & 1)) {
                    *(float2*)c1p = make_float2(v2, v3);
                } else { c1p[0] = v2; c1p[1] = v3; }
            } else {
                if (cn < VOCAB) {
                    float b0 = __ldg(bias + cn);
                    c0p[0] = acc[mt][nt][0] + b0;
                    c1p[0] = acc[mt][nt][2] + b0;
                }
                if (cn + 1 < VOCAB) {
                    float b1 = __ldg(bias + cn + 1);
                    c0p[1] = acc[mt][nt][1] + b1;
                    c1p[1] = acc[mt][nt][3] + b1;
                }
            }
        }
    }
}

// ============================================================
extern "C" void kernel_launch(void* const* d_in, const int* in_sizes, int n_in,
                              void* d_out, int out_size)
{
    const float* x    = (const float*)d_in[0];
    const float* Wg   = (const float*)d_in[1];
    const float* bg   = (const float*)d_in[2];
    const float* We   = (const float*)d_in[3];
    const float* be   = (const float*)d_in[4];
    const float* Wo   = (const float*)d_in[5];
    const float* bo   = (const float*)d_in[6];
    const float* Wout = (const float*)d_in[7];
    const float* bout = (const float*)d_in[8];
    float* out = (float*)d_out;

    const int ctx_smem  = 16*DIN*4 + 16*256*4 + 16*8*4 + 16*32*4;   // 154112
    const int gemm_smem = 3 * STG_B;                                 // 165888
    cudaFuncSetAttribute(fused_ctx_kernel, cudaFuncAttributeMaxDynamicSharedMemorySize, ctx_smem);
    cudaFuncSetAttribute(gemm_mma_kernel,  cudaFuncAttributeMaxDynamicSharedMemorySize, gemm_smem);

    convert_wout_kernel<<<dim3(16, NT128), 256>>>(Wout);
    fused_ctx_kernel<<<BATCH/16, 256, ctx_smem>>>(x, Wg, bg, We, be, Wo, bo);
    topk_gain_kernel<<<1, 256>>>();
    convert_ctx_kernel<<<(BATCH*HID/2)/256, 256>>>();
    gemm_mma_kernel<<<dim3(MT128, NT128), 256, gemm_smem>>>(bout, out);
}

// round 7
// speedup vs baseline: 4.2111x; 1.3789x over previous
#include <cuda_runtime.h>
#include <cuda_fp16.h>
#include <math.h>
#include <stdint.h>

#define BATCH 2048
#define FEAT  2048
#define HARM  32
#define DIN   (FEAT + 2*HARM)   /* 2112 */
#define NEXP  8
#define EDIM  32
#define HID   1024
#define VOCAB 50257
#define NPAD  50432             /* 394 * 128 */
#define NT128 394
#define MT128 16

// ---------------- device scratch (no allocations allowed) ----------------
__device__ __align__(16) float  g_ctx[BATCH * HID];          // 8 MB
__device__ __align__(16) float  g_gain[HID];
__device__ __align__(16) __half g_A_hi[BATCH * HID];         // [2048][1024]
__device__ __align__(16) __half g_B_hi[(size_t)NPAD * HID];  // [NPAD][1024] (Wout^T)

__device__ __forceinline__ uint32_t smem_u32(const void* p) {
    uint32_t a;
    asm("{ .reg .u64 t; cvta.to.shared.u64 t, %1; cvt.u32.u64 %0, t; }" : "=r"(a) : "l"(p));
    return a;
}

#define LDSM_X4(r, a) asm volatile( \
    "ldmatrix.sync.aligned.m8n8.x4.shared.b16 {%0,%1,%2,%3}, [%4];" \
    : "=r"((r)[0]),"=r"((r)[1]),"=r"((r)[2]),"=r"((r)[3]) : "r"(a))
#define MMA16816(c, a, b) asm volatile( \
    "mma.sync.aligned.m16n8k16.row.col.f32.f16.f16.f32 " \
    "{%0,%1,%2,%3},{%4,%5,%6,%7},{%8,%9},{%0,%1,%2,%3};" \
    : "+f"((c)[0]),"+f"((c)[1]),"+f"((c)[2]),"+f"((c)[3]) \
    : "r"((a)[0]),"r"((a)[1]),"r"((a)[2]),"r"((a)[3]), "r"((b)[0]),"r"((b)[1]))
#define CP_ASYNC16(d, s) asm volatile( \
    "cp.async.cg.shared.global [%0], [%1], 16;" :: "r"(d), "l"(s) : "memory")
#define CP_COMMIT() asm volatile("cp.async.commit_group;" ::: "memory")
#define CP_WAIT2()  asm volatile("cp.async.wait_group 2;" ::: "memory")
#define CP_WAIT0()  asm volatile("cp.async.wait_group 0;" ::: "memory")

// ============================================================
// Kernel 1: fused ctx — 16 samples per block, 128 blocks
// ============================================================
__global__ __launch_bounds__(256) void fused_ctx_kernel(
    const float* __restrict__ x,
    const float* __restrict__ Wg, const float* __restrict__ bg,
    const float* __restrict__ We, const float* __restrict__ be,
    const float* __restrict__ Wo, const float* __restrict__ bo)
{
    extern __shared__ __align__(16) char sm[];
    float* enh    = (float*)sm;                          // [16][2112]
    float* eo_s   = (float*)(sm + 16*DIN*4);             // [16][256]
    float* logits = (float*)(sm + 16*DIN*4 + 16*256*4);  // [16][8]
    float* mixed  = logits + 16*8;                       // [16][32]

    const int t = threadIdx.x;
    const int wid = t >> 5, lane = t & 31;
    const int b0 = blockIdx.x * 16;

    for (int sh = 0; sh < 2; sh++) {
        int s = wid * 2 + sh;
        const float4* xr = (const float4*)(x + (size_t)(b0 + s) * FEAT);
        float* er = enh + s * DIN;
        float sum = 0.f;
        #pragma unroll 4
        for (int i = lane; i < FEAT/4; i += 32) {
            float4 v = xr[i];
            *(float4*)(er + 4*i) = v;
            sum += (v.x + v.y) + (v.z + v.w);
        }
        #pragma unroll
        for (int o = 16; o > 0; o >>= 1) sum += __shfl_xor_sync(0xffffffffu, sum, o);
        float mean = sum * (1.0f / FEAT);
        float base = 43.98229715025711f * mean;   // 2*pi*7
        float ph = base * (float)(lane + 1);
        er[FEAT + lane]        = cosf(ph);
        er[FEAT + HARM + lane] = sinf(ph);
    }
    __syncthreads();

    for (int jj = t; jj < NEXP + NEXP*EDIM; jj += 256) {
        float acc[16];
        #pragma unroll
        for (int s = 0; s < 16; s++) acc[s] = 0.f;
        const float* wp; long stride;
        if (jj < NEXP) { wp = Wg + jj; stride = NEXP; }
        else { int e = (jj - NEXP) >> 5, h = (jj - NEXP) & 31;
               wp = We + (size_t)e * DIN * EDIM + h; stride = EDIM; }
        for (int d = 0; d < DIN; d += 4) {
            float w0 = wp[(long)(d+0)*stride];
            float w1 = wp[(long)(d+1)*stride];
            float w2 = wp[(long)(d+2)*stride];
            float w3 = wp[(long)(d+3)*stride];
            #pragma unroll
            for (int s = 0; s < 16; s++) {
                float4 ev = *(const float4*)(enh + s*DIN + d);
                float a = acc[s];
                a = fmaf(ev.x, w0, a); a = fmaf(ev.y, w1, a);
                a = fmaf(ev.z, w2, a); a = fmaf(ev.w, w3, a);
                acc[s] = a;
            }
        }
        if (jj < NEXP) {
            #pragma unroll
            for (int s = 0; s < 16; s++) logits[s*8 + jj] = acc[s] + bg[jj];
        } else {
            #pragma unroll
            for (int s = 0; s < 16; s++) eo_s[s*256 + (jj - NEXP)] = acc[s] + be[jj - NEXP];
        }
    }
    __syncthreads();

    if (t < 16) {
        float* lg = logits + t*8;
        float mx = lg[0];
        #pragma unroll
        for (int e = 1; e < 8; e++) mx = fmaxf(mx, lg[e]);
        float ss = 0.f;
        #pragma unroll
        for (int e = 0; e < 8; e++) { float ex = expf(lg[e] - mx); lg[e] = ex; ss += ex; }
        float inv = 1.0f / ss;
        #pragma unroll
        for (int e = 0; e < 8; e++) lg[e] *= inv;
    }
    __syncthreads();

    for (int v = t; v < 16*32; v += 256) {
        int s = v >> 5, h = v & 31;
        float m = 0.f;
        #pragma unroll
        for (int e = 0; e < 8; e++) m = fmaf(logits[s*8 + e], eo_s[s*256 + e*32 + h], m);
        mixed[v] = m;
    }
    __syncthreads();

    for (int it = 0; it < 4; it++) {
        int o = t + it * 256;
        float acc[16];
        float bb = bo[o];
        #pragma unroll
        for (int s = 0; s < 16; s++) acc[s] = bb;
        for (int k = 0; k < EDIM; k++) {
            float w = Wo[(size_t)k * HID + o];
            #pragma unroll
            for (int s = 0; s < 16; s++) acc[s] = fmaf(mixed[s*32 + k], w, acc[s]);
        }
        #pragma unroll
        for (int s = 0; s < 16; s++)
            g_ctx[(size_t)(b0 + s) * HID + o] = tanhf(acc[s]);
    }
}

// ============================================================
// Kernel 2: top-20 of ctx[0,:] -> gain (spiking scan collapses)
// ============================================================
__global__ __launch_bounds__(256) void topk_gain_kernel()
{
    __shared__ float vals[HID];
    __shared__ float rv[256];
    __shared__ int   ri[256];
    const int t = threadIdx.x;
    for (int i = t; i < HID; i += 256) { vals[i] = g_ctx[i]; g_gain[i] = 1.0f; }
    __syncthreads();
    for (int it = 0; it < 20; it++) {
        float best = -1e30f; int bi = 0;
        for (int i = t; i < HID; i += 256)
            if (vals[i] > best) { best = vals[i]; bi = i; }
        rv[t] = best; ri[t] = bi;
        __syncthreads();
        for (int s = 128; s > 0; s >>= 1) {
            if (t < s && rv[t + s] > rv[t]) { rv[t] = rv[t + s]; ri[t] = ri[t + s]; }
            __syncthreads();
        }
        if (t == 0) { g_gain[ri[0]] = 2.0f; vals[ri[0]] = -1e30f; }
        __syncthreads();
    }
}

// ============================================================
// Kernel 3: convert ctx*gain -> fp16, plain [M][K]
// ============================================================
__global__ __launch_bounds__(256) void convert_ctx_kernel()
{
    int idx = blockIdx.x * 256 + threadIdx.x;
    int mr = idx >> 9;
    int k  = (idx & 511) * 2;
    float2 v = *(const float2*)(g_ctx + (size_t)mr * HID + k);
    float2 g = *(const float2*)(g_gain + k);
    __half h0 = __float2half_rn(v.x * g.x);
    __half h1 = __float2half_rn(v.y * g.y);
    uint32_t hi = (uint32_t)__half_as_ushort(h0) | ((uint32_t)__half_as_ushort(h1) << 16);
    *(uint32_t*)((__half*)g_A_hi + (size_t)mr * HID + k) = hi;
}

// ============================================================
// Kernel 4: Wout [K][N] f32 -> g_B_hi [NPAD][K] fp16 (transpose)
// ============================================================
__global__ __launch_bounds__(256) void convert_wout_kernel(const float* __restrict__ W)
{
    __shared__ uint16_t s_hi[128][66];
    const int t = threadIdx.x;
    const int k0 = blockIdx.x * 64;
    const int n0 = blockIdx.y * 128;

    for (int it = 0; it < 32; it++) {
        int idx = it * 256 + t;        // 64k x 128n
        int k = idx >> 7, n = idx & 127;
        int gn = n0 + n;
        float v = (gn < VOCAB) ? __ldg(W + (size_t)(k0 + k) * VOCAB + gn) : 0.f;
        s_hi[n][k] = __half_as_ushort(__float2half_rn(v));
    }
    __syncthreads();

    for (int it = 0; it < 16; it++) {
        int u = it * 256 + t;          // 128 n-rows x 32 uint32
        int nn = u >> 5, ku = (u & 31) * 2;
        uint32_t hv = *(uint32_t*)&s_hi[nn][ku];
        size_t e = (size_t)(n0 + nn) * HID + k0 + ku;
        *(uint32_t*)((__half*)g_B_hi + e) = hv;
    }
}

// ============================================================
// Kernel 5: out = A @ B^T + bias via mma.sync fp16 (1 product)
// CTA 128x128, BK=64, 4-stage cp.async pipeline, 8 warps of 32x64
// B fragments via ldmatrix.x4 over nt-pairs (half the LDSM count)
// ============================================================
#define BK 64
#define SROW 72                        /* fp16 per smem row (pad 8) */
#define ARR_B (128 * SROW * 2)         /* 18432 B per array */
#define STG_B (2 * ARR_B)              /* Ah | Bh = 36864 B */
#define NSTG 4
#define NCHUNK (HID / BK)              /* 16 */

__global__ __launch_bounds__(256) void gemm_mma_kernel(
    const float* __restrict__ bias, float* __restrict__ C)
{
    extern __shared__ __align__(16) char sm[];
    const uint32_t sb = smem_u32(sm);
    const int t = threadIdx.x, lane = t & 31, wid = t >> 5;
    const int m0 = blockIdx.x * 128, n0 = blockIdx.y * 128;
    const int m0w = (wid & 3) * 32, n0w = (wid >> 2) * 64;

    float acc[2][8][4];
    #pragma unroll
    for (int i = 0; i < 2; i++)
        #pragma unroll
        for (int j = 0; j < 8; j++)
            #pragma unroll
            for (int q = 0; q < 4; q++) acc[i][j][q] = 0.f;

    const __half* srcA = g_A_hi + (size_t)m0 * HID;
    const __half* srcB = g_B_hi + (size_t)n0 * HID;

    auto issue = [&](int c) {
        uint32_t stg = sb + (uint32_t)(c & (NSTG - 1)) * STG_B;
        int k0 = c * BK;
        #pragma unroll
        for (int a = 0; a < 2; a++) {
            uint32_t dbase = stg + a * ARR_B;
            const __half* gp = (a == 0 ? srcA : srcB) + k0;
            #pragma unroll
            for (int it = 0; it < 4; it++) {
                int idx = it * 256 + t;
                int row = idx >> 3, seg = idx & 7;
                uint32_t d = dbase + row * (SROW * 2) + seg * 16;
                CP_ASYNC16(d, gp + (size_t)row * HID + seg * 8);
            }
        }
        CP_COMMIT();
    };

    issue(0); issue(1); issue(2);
    for (int c = 0; c < NCHUNK; c++) {
        if (c + 3 < NCHUNK) { CP_WAIT2(); } else { CP_WAIT0(); }
        __syncthreads();
        if (c + 3 < NCHUNK) issue(c + 3);

        uint32_t stg = sb + (uint32_t)(c & (NSTG - 1)) * STG_B;
        uint32_t pAh = stg, pBh = stg + ARR_B;

        #pragma unroll
        for (int ks = 0; ks < 4; ks++) {
            int kb = ks * 16;
            uint32_t acol = (uint32_t)(kb + ((lane >> 4) << 3)) * 2;

            uint32_t ah[2][4];
            #pragma unroll
            for (int mt = 0; mt < 2; mt++) {
                uint32_t ra = (uint32_t)(m0w + mt*16 + (lane & 15)) * (SROW*2) + acol;
                LDSM_X4(ah[mt], pAh + ra);
            }
            // B: 4x ldmatrix.x4, each covers an nt-pair (16 rows x 2 k-halves)
            uint32_t bh[8][2];
            {
                int g = lane >> 3;                 // 0..3
                int browoff = (g & 1) * 8 + (lane & 7);
                int bcoloff = (g >> 1) * 8;
                #pragma unroll
                for (int np = 0; np < 4; np++) {
                    uint32_t r4[4];
                    uint32_t rb = (uint32_t)(n0w + np*16 + browoff) * (SROW*2)
                                + (uint32_t)(kb + bcoloff) * 2;
                    LDSM_X4(r4, pBh + rb);
                    bh[2*np  ][0] = r4[0]; bh[2*np  ][1] = r4[2];
                    bh[2*np+1][0] = r4[1]; bh[2*np+1][1] = r4[3];
                }
            }
            #pragma unroll
            for (int mt = 0; mt < 2; mt++)
                #pragma unroll
                for (int nt = 0; nt < 8; nt++)
                    MMA16816(acc[mt][nt], ah[mt], bh[nt]);
        }
        __syncthreads();
    }

    // ---- epilogue: + bias, store ----
    const bool full = (n0 + 128 <= VOCAB);
    #pragma unroll
    for (int mt = 0; mt < 2; mt++) {
        int r0 = m0 + m0w + mt*16 + (lane >> 2);
        #pragma unroll
        for (int nt = 0; nt < 8; nt++) {
            int cn = n0 + n0w + nt*8 + ((lane & 3) << 1);
            float* c0p = C + (size_t)r0 * VOCAB + cn;
            float* c1p = c0p + (size_t)8 * VOCAB;
            if (full) {
                float b0 = __ldg(bias + cn), b1 = __ldg(bias + cn + 1);
                float v0 = acc[mt][nt][0] + b0, v1 = acc[mt][nt][1] + b1;
                float v2 = acc[mt][nt][2] + b0, v3 = acc[mt][nt][3] + b1;
                if (!(((size_t)r0 * VOCAB + cn) & 1)) {
                    *(float2*)c0p = make_float2(v0, v1);
                } else { c0p[0] = v0; c0p[1] = v1; }
                if (!(((size_t)(r0+8) * VOCAB + cn) & 1)) {
                    *(float2*)c1p = make_float2(v2, v3);
                } else { c1p[0] = v2; c1p[1] = v3; }
            } else {
                if (cn < VOCAB) {
                    float b0 = __ldg(bias + cn);
                    c0p[0] = acc[mt][nt][0] + b0;
                    c1p[0] = acc[mt][nt][2] + b0;
                }
                if (cn + 1 < VOCAB) {
                    float b1 = __ldg(bias + cn + 1);
                    c0p[1] = acc[mt][nt][1] + b1;
                    c1p[1] = acc[mt][nt][3] + b1;
                }
            }
        }
    }
}

// ============================================================
extern "C" void kernel_launch(void* const* d_in, const int* in_sizes, int n_in,
                              void* d_out, int out_size)
{
    const float* x    = (const float*)d_in[0];
    const float* Wg   = (const float*)d_in[1];
    const float* bg   = (const float*)d_in[2];
    const float* We   = (const float*)d_in[3];
    const float* be   = (const float*)d_in[4];
    const float* Wo   = (const float*)d_in[5];
    const float* bo   = (const float*)d_in[6];
    const float* Wout = (const float*)d_in[7];
    const float* bout = (const float*)d_in[8];
    float* out = (float*)d_out;

    const int ctx_smem  = 16*DIN*4 + 16*256*4 + 16*8*4 + 16*32*4;   // 154112
    const int gemm_smem = NSTG * STG_B;                              // 147456
    cudaFuncSetAttribute(fused_ctx_kernel, cudaFuncAttributeMaxDynamicSharedMemorySize, ctx_smem);
    cudaFuncSetAttribute(gemm_mma_kernel,  cudaFuncAttributeMaxDynamicSharedMemorySize, gemm_smem);

    convert_wout_kernel<<<dim3(16, NT128), 256>>>(Wout);
    fused_ctx_kernel<<<BATCH/16, 256, ctx_smem>>>(x, Wg, bg, We, be, Wo, bo);
    topk_gain_kernel<<<1, 256>>>();
    convert_ctx_kernel<<<(BATCH*HID/2)/256, 256>>>();
    gemm_mma_kernel<<<dim3(MT128, NT128), 256, gemm_smem>>>(bout, out);
}

// round 8
// speedup vs baseline: 4.9632x; 1.1786x over previous
#include <cuda_runtime.h>
#include <cuda_fp16.h>
#include <math.h>
#include <stdint.h>

#define BATCH 2048
#define FEAT  2048
#define HARM  32
#define DIN   (FEAT + 2*HARM)   /* 2112 */
#define NEXP  8
#define EDIM  32
#define HID   1024
#define VOCAB 50257
#define NPAD  50432             /* 394 * 128 */
#define NT128 394
#define MT128 16

// ---------------- device scratch (no allocations allowed) ----------------
__device__ __align__(16) float  g_ctx[BATCH * HID];          // 8 MB
__device__ __align__(16) float  g_gain[HID];
__device__ __align__(16) __half g_A_hi[BATCH * HID];         // [2048][1024]
__device__ __align__(16) __half g_B_hi[(size_t)NPAD * HID];  // [NPAD][1024] (Wout^T)

__device__ __forceinline__ uint32_t smem_u32(const void* p) {
    uint32_t a;
    asm("{ .reg .u64 t; cvta.to.shared.u64 t, %1; cvt.u32.u64 %0, t; }" : "=r"(a) : "l"(p));
    return a;
}

#define LDSM_X4(r, a) asm volatile( \
    "ldmatrix.sync.aligned.m8n8.x4.shared.b16 {%0,%1,%2,%3}, [%4];" \
    : "=r"((r)[0]),"=r"((r)[1]),"=r"((r)[2]),"=r"((r)[3]) : "r"(a))
#define MMA16816(c, a, b) asm volatile( \
    "mma.sync.aligned.m16n8k16.row.col.f32.f16.f16.f32 " \
    "{%0,%1,%2,%3},{%4,%5,%6,%7},{%8,%9},{%0,%1,%2,%3};" \
    : "+f"((c)[0]),"+f"((c)[1]),"+f"((c)[2]),"+f"((c)[3]) \
    : "r"((a)[0]),"r"((a)[1]),"r"((a)[2]),"r"((a)[3]), "r"((b)[0]),"r"((b)[1]))
#define CP_ASYNC16(d, s) asm volatile( \
    "cp.async.cg.shared.global [%0], [%1], 16;" :: "r"(d), "l"(s) : "memory")
#define CP_COMMIT() asm volatile("cp.async.commit_group;" ::: "memory")
#define CP_WAIT1()  asm volatile("cp.async.wait_group 1;" ::: "memory")
#define CP_WAIT0()  asm volatile("cp.async.wait_group 0;" ::: "memory")

// ============================================================
// Kernel 1: fused ctx — 16 samples per block, 128 blocks
// ============================================================
__global__ __launch_bounds__(256) void fused_ctx_kernel(
    const float* __restrict__ x,
    const float* __restrict__ Wg, const float* __restrict__ bg,
    const float* __restrict__ We, const float* __restrict__ be,
    const float* __restrict__ Wo, const float* __restrict__ bo)
{
    extern __shared__ __align__(16) char sm[];
    float* enh    = (float*)sm;                          // [16][2112]
    float* eo_s   = (float*)(sm + 16*DIN*4);             // [16][256]
    float* logits = (float*)(sm + 16*DIN*4 + 16*256*4);  // [16][8]
    float* mixed  = logits + 16*8;                       // [16][32]

    const int t = threadIdx.x;
    const int wid = t >> 5, lane = t & 31;
    const int b0 = blockIdx.x * 16;

    for (int sh = 0; sh < 2; sh++) {
        int s = wid * 2 + sh;
        const float4* xr = (const float4*)(x + (size_t)(b0 + s) * FEAT);
        float* er = enh + s * DIN;
        float sum = 0.f;
        #pragma unroll 4
        for (int i = lane; i < FEAT/4; i += 32) {
            float4 v = xr[i];
            *(float4*)(er + 4*i) = v;
            sum += (v.x + v.y) + (v.z + v.w);
        }
        #pragma unroll
        for (int o = 16; o > 0; o >>= 1) sum += __shfl_xor_sync(0xffffffffu, sum, o);
        float mean = sum * (1.0f / FEAT);
        float base = 43.98229715025711f * mean;   // 2*pi*7
        float ph = base * (float)(lane + 1);
        er[FEAT + lane]        = cosf(ph);
        er[FEAT + HARM + lane] = sinf(ph);
    }
    __syncthreads();

    for (int jj = t; jj < NEXP + NEXP*EDIM; jj += 256) {
        float acc[16];
        #pragma unroll
        for (int s = 0; s < 16; s++) acc[s] = 0.f;
        const float* wp; long stride;
        if (jj < NEXP) { wp = Wg + jj; stride = NEXP; }
        else { int e = (jj - NEXP) >> 5, h = (jj - NEXP) & 31;
               wp = We + (size_t)e * DIN * EDIM + h; stride = EDIM; }
        for (int d = 0; d < DIN; d += 4) {
            float w0 = wp[(long)(d+0)*stride];
            float w1 = wp[(long)(d+1)*stride];
            float w2 = wp[(long)(d+2)*stride];
            float w3 = wp[(long)(d+3)*stride];
            #pragma unroll
            for (int s = 0; s < 16; s++) {
                float4 ev = *(const float4*)(enh + s*DIN + d);
                float a = acc[s];
                a = fmaf(ev.x, w0, a); a = fmaf(ev.y, w1, a);
                a = fmaf(ev.z, w2, a); a = fmaf(ev.w, w3, a);
                acc[s] = a;
            }
        }
        if (jj < NEXP) {
            #pragma unroll
            for (int s = 0; s < 16; s++) logits[s*8 + jj] = acc[s] + bg[jj];
        } else {
            #pragma unroll
            for (int s = 0; s < 16; s++) eo_s[s*256 + (jj - NEXP)] = acc[s] + be[jj - NEXP];
        }
    }
    __syncthreads();

    if (t < 16) {
        float* lg = logits + t*8;
        float mx = lg[0];
        #pragma unroll
        for (int e = 1; e < 8; e++) mx = fmaxf(mx, lg[e]);
        float ss = 0.f;
        #pragma unroll
        for (int e = 0; e < 8; e++) { float ex = expf(lg[e] - mx); lg[e] = ex; ss += ex; }
        float inv = 1.0f / ss;
        #pragma unroll
        for (int e = 0; e < 8; e++) lg[e] *= inv;
    }
    __syncthreads();

    for (int v = t; v < 16*32; v += 256) {
        int s = v >> 5, h = v & 31;
        float m = 0.f;
        #pragma unroll
        for (int e = 0; e < 8; e++) m = fmaf(logits[s*8 + e], eo_s[s*256 + e*32 + h], m);
        mixed[v] = m;
    }
    __syncthreads();

    for (int it = 0; it < 4; it++) {
        int o = t + it * 256;
        float acc[16];
        float bb = bo[o];
        #pragma unroll
        for (int s = 0; s < 16; s++) acc[s] = bb;
        for (int k = 0; k < EDIM; k++) {
            float w = Wo[(size_t)k * HID + o];
            #pragma unroll
            for (int s = 0; s < 16; s++) acc[s] = fmaf(mixed[s*32 + k], w, acc[s]);
        }
        #pragma unroll
        for (int s = 0; s < 16; s++)
            g_ctx[(size_t)(b0 + s) * HID + o] = tanhf(acc[s]);
    }
}

// ============================================================
// Kernel 2: top-20 of ctx[0,:] -> gain (spiking scan collapses)
// ============================================================
__global__ __launch_bounds__(256) void topk_gain_kernel()
{
    __shared__ float vals[HID];
    __shared__ float rv[256];
    __shared__ int   ri[256];
    const int t = threadIdx.x;
    for (int i = t; i < HID; i += 256) { vals[i] = g_ctx[i]; g_gain[i] = 1.0f; }
    __syncthreads();
    for (int it = 0; it < 20; it++) {
        float best = -1e30f; int bi = 0;
        for (int i = t; i < HID; i += 256)
            if (vals[i] > best) { best = vals[i]; bi = i; }
        rv[t] = best; ri[t] = bi;
        __syncthreads();
        for (int s = 128; s > 0; s >>= 1) {
            if (t < s && rv[t + s] > rv[t]) { rv[t] = rv[t + s]; ri[t] = ri[t + s]; }
            __syncthreads();
        }
        if (t == 0) { g_gain[ri[0]] = 2.0f; vals[ri[0]] = -1e30f; }
        __syncthreads();
    }
}

// ============================================================
// Kernel 3: convert ctx*gain -> fp16, plain [M][K]
// ============================================================
__global__ __launch_bounds__(256) void convert_ctx_kernel()
{
    int idx = blockIdx.x * 256 + threadIdx.x;
    int mr = idx >> 9;
    int k  = (idx & 511) * 2;
    float2 v = *(const float2*)(g_ctx + (size_t)mr * HID + k);
    float2 g = *(const float2*)(g_gain + k);
    __half h0 = __float2half_rn(v.x * g.x);
    __half h1 = __float2half_rn(v.y * g.y);
    uint32_t hi = (uint32_t)__half_as_ushort(h0) | ((uint32_t)__half_as_ushort(h1) << 16);
    *(uint32_t*)((__half*)g_A_hi + (size_t)mr * HID + k) = hi;
}

// ============================================================
// Kernel 4: Wout [K][N] f32 -> g_B_hi [NPAD][K] fp16 (transpose)
// ============================================================
__global__ __launch_bounds__(256) void convert_wout_kernel(const float* __restrict__ W)
{
    __shared__ uint16_t s_hi[128][66];
    const int t = threadIdx.x;
    const int k0 = blockIdx.x * 64;
    const int n0 = blockIdx.y * 128;

    for (int it = 0; it < 32; it++) {
        int idx = it * 256 + t;        // 64k x 128n
        int k = idx >> 7, n = idx & 127;
        int gn = n0 + n;
        float v = (gn < VOCAB) ? __ldg(W + (size_t)(k0 + k) * VOCAB + gn) : 0.f;
        s_hi[n][k] = __half_as_ushort(__float2half_rn(v));
    }
    __syncthreads();

    for (int it = 0; it < 16; it++) {
        int u = it * 256 + t;          // 128 n-rows x 32 uint32
        int nn = u >> 5, ku = (u & 31) * 2;
        uint32_t hv = *(uint32_t*)&s_hi[nn][ku];
        size_t e = (size_t)(n0 + nn) * HID + k0 + ku;
        *(uint32_t*)((__half*)g_B_hi + e) = hv;
    }
}

// ============================================================
// Kernel 5: out = A @ B^T + bias via mma.sync fp16
// CTA 128x128, BK=64, 3-stage cp.async pipeline, ONE sync per chunk,
// 2 CTAs/SM for latency hiding. 8 warps of 32x64.
// ============================================================
#define BK 64
#define SROW 72                        /* fp16 per smem row (pad 8) */
#define ARR_B (128 * SROW * 2)         /* 18432 B per array */
#define STG_B (2 * ARR_B)              /* Ah | Bh = 36864 B */
#define NSTG 3
#define NCHUNK (HID / BK)              /* 16 */

__global__ __launch_bounds__(256, 2) void gemm_mma_kernel(
    const float* __restrict__ bias, float* __restrict__ C)
{
    extern __shared__ __align__(16) char sm[];
    const uint32_t sb = smem_u32(sm);
    const int t = threadIdx.x, lane = t & 31, wid = t >> 5;
    const int m0 = blockIdx.x * 128, n0 = blockIdx.y * 128;
    const int m0w = (wid & 3) * 32, n0w = (wid >> 2) * 64;

    float acc[2][8][4];
    #pragma unroll
    for (int i = 0; i < 2; i++)
        #pragma unroll
        for (int j = 0; j < 8; j++)
            #pragma unroll
            for (int q = 0; q < 4; q++) acc[i][j][q] = 0.f;

    const __half* srcA = g_A_hi + (size_t)m0 * HID;
    const __half* srcB = g_B_hi + (size_t)n0 * HID;

    auto issue = [&](int c) {
        uint32_t stg = sb + (uint32_t)(c % NSTG) * STG_B;
        int k0 = c * BK;
        #pragma unroll
        for (int a = 0; a < 2; a++) {
            uint32_t dbase = stg + a * ARR_B;
            const __half* gp = (a == 0 ? srcA : srcB) + k0;
            #pragma unroll
            for (int it = 0; it < 4; it++) {
                int idx = it * 256 + t;
                int row = idx >> 3, seg = idx & 7;
                uint32_t d = dbase + row * (SROW * 2) + seg * 16;
                CP_ASYNC16(d, gp + (size_t)row * HID + seg * 8);
            }
        }
        CP_COMMIT();
    };

    issue(0); issue(1);
    for (int c = 0; c < NCHUNK; c++) {
        if (c + 1 < NCHUNK) { CP_WAIT1(); } else { CP_WAIT0(); }
        __syncthreads();
        // stage (c+2)%3 was fully consumed at iteration c-1 (fenced by the
        // sync above), so it's safe to refill it now — no trailing sync.
        if (c + 2 < NCHUNK) issue(c + 2);

        uint32_t stg = sb + (uint32_t)(c % NSTG) * STG_B;
        uint32_t pAh = stg, pBh = stg + ARR_B;

        #pragma unroll
        for (int ks = 0; ks < 4; ks++) {
            int kb = ks * 16;
            uint32_t acol = (uint32_t)(kb + ((lane >> 4) << 3)) * 2;

            uint32_t ah[2][4];
            #pragma unroll
            for (int mt = 0; mt < 2; mt++) {
                uint32_t ra = (uint32_t)(m0w + mt*16 + (lane & 15)) * (SROW*2) + acol;
                LDSM_X4(ah[mt], pAh + ra);
            }
            // B: 4x ldmatrix.x4, each covers an nt-pair (16 rows x 2 k-halves)
            uint32_t bh[8][2];
            {
                int g = lane >> 3;                 // 0..3
                int browoff = (g & 1) * 8 + (lane & 7);
                int bcoloff = (g >> 1) * 8;
                #pragma unroll
                for (int np = 0; np < 4; np++) {
                    uint32_t r4[4];
                    uint32_t rb = (uint32_t)(n0w + np*16 + browoff) * (SROW*2)
                                + (uint32_t)(kb + bcoloff) * 2;
                    LDSM_X4(r4, pBh + rb);
                    bh[2*np  ][0] = r4[0]; bh[2*np  ][1] = r4[2];
                    bh[2*np+1][0] = r4[1]; bh[2*np+1][1] = r4[3];
                }
            }
            #pragma unroll
            for (int mt = 0; mt < 2; mt++)
                #pragma unroll
                for (int nt = 0; nt < 8; nt++)
                    MMA16816(acc[mt][nt], ah[mt], bh[nt]);
        }
    }

    // ---- epilogue: + bias, store ----
    const bool full = (n0 + 128 <= VOCAB);
    #pragma unroll
    for (int mt = 0; mt < 2; mt++) {
        int r0 = m0 + m0w + mt*16 + (lane >> 2);
        #pragma unroll
        for (int nt = 0; nt < 8; nt++) {
            int cn = n0 + n0w + nt*8 + ((lane & 3) << 1);
            float* c0p = C + (size_t)r0 * VOCAB + cn;
            float* c1p = c0p + (size_t)8 * VOCAB;
            if (full) {
                float b0 = __ldg(bias + cn), b1 = __ldg(bias + cn + 1);
                float v0 = acc[mt][nt][0] + b0, v1 = acc[mt][nt][1] + b1;
                float v2 = acc[mt][nt][2] + b0, v3 = acc[mt][nt][3] + b1;
                if (!(((size_t)r0 * VOCAB + cn) & 1)) {
                    *(float2*)c0p = make_float2(v0, v1);
                } else { c0p[0] = v0; c0p[1] = v1; }
                if (!(((size_t)(r0+8) * VOCAB + cn) & 1)) {
                    *(float2*)c1p = make_float2(v2, v3);
                } else { c1p[0] = v2; c1p[1] = v3; }
            } else {
                if (cn < VOCAB) {
                    float b0 = __ldg(bias + cn);
                    c0p[0] = acc[mt][nt][0] + b0;
                    c1p[0] = acc[mt][nt][2] + b0;
                }
                if (cn + 1 < VOCAB) {
                    float b1 = __ldg(bias + cn + 1);
                    c0p[1] = acc[mt][nt][1] + b1;
                    c1p[1] = acc[mt][nt][3] + b1;
                }
            }
        }
    }
}

// ============================================================
extern "C" void kernel_launch(void* const* d_in, const int* in_sizes, int n_in,
                              void* d_out, int out_size)
{
    const float* x    = (const float*)d_in[0];
    const float* Wg   = (const float*)d_in[1];
    const float* bg   = (const float*)d_in[2];
    const float* We   = (const float*)d_in[3];
    const float* be   = (const float*)d_in[4];
    const float* Wo   = (const float*)d_in[5];
    const float* bo   = (const float*)d_in[6];
    const float* Wout = (const float*)d_in[7];
    const float* bout = (const float*)d_in[8];
    float* out = (float*)d_out;

    const int ctx_smem  = 16*DIN*4 + 16*256*4 + 16*8*4 + 16*32*4;   // 154112
    const int gemm_smem = NSTG * STG_B;                              // 110592
    cudaFuncSetAttribute(fused_ctx_kernel, cudaFuncAttributeMaxDynamicSharedMemorySize, ctx_smem);
    cudaFuncSetAttribute(gemm_mma_kernel,  cudaFuncAttributeMaxDynamicSharedMemorySize, gemm_smem);

    convert_wout_kernel<<<dim3(16, NT128), 256>>>(Wout);
    fused_ctx_kernel<<<BATCH/16, 256, ctx_smem>>>(x, Wg, bg, We, be, Wo, bo);
    topk_gain_kernel<<<1, 256>>>();
    convert_ctx_kernel<<<(BATCH*HID/2)/256, 256>>>();
    gemm_mma_kernel<<<dim3(MT128, NT128), 256, gemm_smem>>>(bout, out);
}